// round 2
// baseline (speedup 1.0000x reference)
#include <cuda_runtime.h>
#include <cuda_bf16.h>
#include <cstdint>

// Problem shapes (fixed)
#define BATCH_M   8192      // B*S = 4*2048
#define DIM_K     2048      // IN
#define DIM_N     2048      // OUT
#define ID_DIM    64
#define NW_ELEMS  (DIM_N * DIM_K)   // 4,194,304

// Scratch: reconstructed weight [OUT, IN] and bias [OUT]
__device__ float g_W[NW_ELEMS];
__device__ float g_bias[DIM_N];

// ---------------------------------------------------------------------------
// Kernel A: out[i] = dot(P[i, 0:64], coef)  for i in [0, n)
// P rows are 64 contiguous f32 (256 B) -> 16 float4 loads per row.
// ---------------------------------------------------------------------------
__global__ void build_W_kernel(const float* __restrict__ P,
                               const float* __restrict__ coef,
                               float* __restrict__ out, int n) {
    __shared__ float c[ID_DIM];
    if (threadIdx.x < ID_DIM) c[threadIdx.x] = coef[threadIdx.x];
    __syncthreads();

    int i = blockIdx.x * blockDim.x + threadIdx.x;
    int stride = gridDim.x * blockDim.x;
    for (; i < n; i += stride) {
        const float4* row = reinterpret_cast<const float4*>(P + (size_t)i * ID_DIM);
        float acc = 0.f;
#pragma unroll
        for (int j = 0; j < 16; ++j) {
            float4 v = row[j];
            acc += v.x * c[4 * j + 0];
            acc += v.y * c[4 * j + 1];
            acc += v.z * c[4 * j + 2];
            acc += v.w * c[4 * j + 3];
        }
        out[i] = acc;
    }
}

// ---------------------------------------------------------------------------
// Kernel B: C[m, n] = sum_k A[m, k] * B[n, k] + bias[n]
// A: [8192, 2048] row-major (x), B: [2048, 2048] row-major (W), both K-inner.
// Tiles: BM=BN=128, BK=16; 256 threads; 8x8 acc per thread.
// ---------------------------------------------------------------------------
__global__ __launch_bounds__(256, 1)
void sgemm_nt_bias(const float* __restrict__ A,
                   const float* __restrict__ B,
                   const float* __restrict__ bias,
                   float* __restrict__ C) {
    constexpr int K = DIM_K;
    constexpr int PAD = 4;
    __shared__ float As[16][128 + PAD];
    __shared__ float Bs[16][128 + PAD];

    const int bm = blockIdx.y;   // 0..63
    const int bn = blockIdx.x;   // 0..15
    const int tid = threadIdx.x;
    const int ty = tid >> 4;     // 0..15
    const int tx = tid & 15;     // 0..15

    const float* Ab = A + (size_t)bm * 128 * K;
    const float* Bb = B + (size_t)bn * 128 * K;

    // Staging: each thread loads 2 float4 from A and 2 from B per BK step.
    const int lrow = tid >> 2;          // 0..63
    const int lc4  = (tid & 3) * 4;     // k offset within BK: 0,4,8,12

    float acc[8][8] = {};

    for (int k0 = 0; k0 < K; k0 += 16) {
#pragma unroll
        for (int half = 0; half < 2; ++half) {
            const int r = lrow + half * 64;
            float4 va = *reinterpret_cast<const float4*>(Ab + (size_t)r * K + k0 + lc4);
            As[lc4 + 0][r] = va.x;
            As[lc4 + 1][r] = va.y;
            As[lc4 + 2][r] = va.z;
            As[lc4 + 3][r] = va.w;
            float4 vb = *reinterpret_cast<const float4*>(Bb + (size_t)r * K + k0 + lc4);
            Bs[lc4 + 0][r] = vb.x;
            Bs[lc4 + 1][r] = vb.y;
            Bs[lc4 + 2][r] = vb.z;
            Bs[lc4 + 3][r] = vb.w;
        }
        __syncthreads();

#pragma unroll
        for (int kk = 0; kk < 16; ++kk) {
            float4 a0 = *reinterpret_cast<const float4*>(&As[kk][ty * 8 + 0]);
            float4 a1 = *reinterpret_cast<const float4*>(&As[kk][ty * 8 + 4]);
            float4 b0 = *reinterpret_cast<const float4*>(&Bs[kk][tx * 8 + 0]);
            float4 b1 = *reinterpret_cast<const float4*>(&Bs[kk][tx * 8 + 4]);
            float af[8] = {a0.x, a0.y, a0.z, a0.w, a1.x, a1.y, a1.z, a1.w};
            float bf[8] = {b0.x, b0.y, b0.z, b0.w, b1.x, b1.y, b1.z, b1.w};
#pragma unroll
            for (int i = 0; i < 8; ++i)
#pragma unroll
                for (int j = 0; j < 8; ++j)
                    acc[i][j] += af[i] * bf[j];
        }
        __syncthreads();
    }

    // Epilogue: add bias, vectorized f32x4 stores.
#pragma unroll
    for (int i = 0; i < 8; ++i) {
        const int row = bm * 128 + ty * 8 + i;
        float* Crow = C + (size_t)row * DIM_N + bn * 128 + tx * 8;
        const float* brow = bias + bn * 128 + tx * 8;
#pragma unroll
        for (int j4 = 0; j4 < 2; ++j4) {
            float4 v;
            v.x = acc[i][j4 * 4 + 0] + brow[j4 * 4 + 0];
            v.y = acc[i][j4 * 4 + 1] + brow[j4 * 4 + 1];
            v.z = acc[i][j4 * 4 + 2] + brow[j4 * 4 + 2];
            v.w = acc[i][j4 * 4 + 3] + brow[j4 * 4 + 3];
            *reinterpret_cast<float4*>(Crow + j4 * 4) = v;
        }
    }
}

// ---------------------------------------------------------------------------
// kernel_launch
// Inputs (metadata order): x [4,2048,2048] f32, P_w [4194304,64] f32,
//                          P_b [2048,64] f32, weight_coef [64] f32,
//                          bias_coef [64] f32.
// Output: f32 [4,2048,2048].
// ---------------------------------------------------------------------------
extern "C" void kernel_launch(void* const* d_in, const int* in_sizes, int n_in,
                              void* d_out, int out_size) {
    const float* x     = (const float*)d_in[0];
    const float* P_w   = (const float*)d_in[1];
    const float* P_b   = (const float*)d_in[2];
    const float* wcoef = (const float*)d_in[3];
    const float* bcoef = (const float*)d_in[4];
    float* out = (float*)d_out;

    float* W = nullptr;
    float* b = nullptr;
    cudaGetSymbolAddress((void**)&W, g_W);
    cudaGetSymbolAddress((void**)&b, g_bias);

    // W reconstruction: 4,194,304 rows. 8192 blocks x 256 threads, grid-stride x2.
    build_W_kernel<<<8192, 256>>>(P_w, wcoef, W, NW_ELEMS);
    // Bias reconstruction: 2048 rows.
    build_W_kernel<<<8, 256>>>(P_b, bcoef, b, DIM_N);

    // GEMM: grid (N/128, M/128) = (16, 64).
    dim3 grid(DIM_N / 128, BATCH_M / 128);
    sgemm_nt_bias<<<grid, 256>>>(x, W, b, out);

    (void)in_sizes; (void)n_in; (void)out_size;
}

// round 4
// speedup vs baseline: 3.9911x; 3.9911x over previous
#include <cuda_runtime.h>
#include <cuda_bf16.h>
#include <cstdint>

// Problem shapes (fixed)
#define BATCH_M   8192      // B*S
#define DIM_K     2048      // IN
#define DIM_N     2048      // OUT
#define ID_DIM    64
#define NW_ELEMS  (DIM_N * DIM_K)

// tcgen05 only exists on the arch-specific ('a') / family targets.
#if defined(__CUDA_ARCH_FEAT_SM103_ALL) || defined(__CUDA_ARCH_FEAT_SM100_ALL) || \
    defined(__CUDA_ARCH_FEAT_SM101_ALL) || defined(__CUDA_ARCH_FEAT_SM110_ALL)
#define HAS_TC 1
#else
#define HAS_TC 0
#endif

// ---------------- scratch (device globals; no allocs allowed) ----------------
__device__ __nv_bfloat16 g_Whi[NW_ELEMS];
__device__ __nv_bfloat16 g_Wlo[NW_ELEMS];
__device__ __nv_bfloat16 g_Xhi[BATCH_M * DIM_K];
__device__ __nv_bfloat16 g_Xlo[BATCH_M * DIM_K];
__device__ float         g_bias[DIM_N];

// ---------------- PTX helpers (only instantiated on HAS_TC passes) ----------
__device__ __forceinline__ uint32_t smem_u32(const void* p) {
    uint32_t a;
    asm("{ .reg .u64 t; cvta.to.shared.u64 t, %1; cvt.u32.u64 %0, t; }" : "=r"(a) : "l"(p));
    return a;
}
#if HAS_TC
__device__ __forceinline__ uint32_t elect_one() {
    uint32_t p;
    asm volatile("{ .reg .pred p; elect.sync _|p, 0xFFFFFFFF; selp.b32 %0,1,0,p; }" : "=r"(p));
    return p;
}
#define MBAR_INIT(addr, cnt) \
    asm volatile("mbarrier.init.shared.b64 [%0], %1;" :: "r"(addr), "r"(cnt) : "memory")
#define MBAR_WAIT(addr, par) do {                                              \
    uint32_t _m = (addr), _p = (par), _d;                                      \
    asm volatile("{ .reg .pred p; mbarrier.try_wait.parity.acquire.cta.shared::cta.b64 p, [%1], %2; selp.b32 %0,1,0,p; }" \
        : "=r"(_d) : "r"(_m), "r"(_p) : "memory");                             \
    if (!_d) {                                                                 \
        asm volatile("{ .reg .pred P1; WL%=: mbarrier.try_wait.parity.acquire.cta.shared::cta.b64 P1, [%0], %1, 0x989680; @P1 bra.uni WD%=; bra.uni WL%=; WD%=: }" \
            :: "r"(_m), "r"(_p) : "memory");                                   \
    } } while (0)
#define TC_COMMIT(addr) \
    asm volatile("tcgen05.commit.cta_group::1.mbarrier::arrive::one.shared::cluster.b64 [%0];" :: "r"(addr) : "memory")
#define TC_ALLOC(saddr, n) \
    asm volatile("tcgen05.alloc.cta_group::1.sync.aligned.shared::cta.b32 [%0], %1;" :: "r"(saddr), "r"(n) : "memory")
#define TC_DEALLOC(t, n) \
    asm volatile("tcgen05.dealloc.cta_group::1.sync.aligned.b32 %0, %1;" :: "r"(t), "r"(n))
#define TC_RELINQ() asm volatile("tcgen05.relinquish_alloc_permit.cta_group::1.sync.aligned;")
#define TC_WAIT_LD() asm volatile("tcgen05.wait::ld.sync.aligned;" ::: "memory")
#define TC_FENCE_AFTER() asm volatile("tcgen05.fence::after_thread_sync;" ::: "memory")

#define TC_LD_X32(r, ta)                                                        \
    asm volatile("tcgen05.ld.sync.aligned.32x32b.x32.b32 "                      \
        "{%0,%1,%2,%3,%4,%5,%6,%7,%8,%9,%10,%11,%12,%13,%14,%15,"               \
        "%16,%17,%18,%19,%20,%21,%22,%23,%24,%25,%26,%27,%28,%29,%30,%31}, [%32];" \
        : "=r"((r)[0]),"=r"((r)[1]),"=r"((r)[2]),"=r"((r)[3]),                  \
          "=r"((r)[4]),"=r"((r)[5]),"=r"((r)[6]),"=r"((r)[7]),                  \
          "=r"((r)[8]),"=r"((r)[9]),"=r"((r)[10]),"=r"((r)[11]),                \
          "=r"((r)[12]),"=r"((r)[13]),"=r"((r)[14]),"=r"((r)[15]),              \
          "=r"((r)[16]),"=r"((r)[17]),"=r"((r)[18]),"=r"((r)[19]),              \
          "=r"((r)[20]),"=r"((r)[21]),"=r"((r)[22]),"=r"((r)[23]),              \
          "=r"((r)[24]),"=r"((r)[25]),"=r"((r)[26]),"=r"((r)[27]),              \
          "=r"((r)[28]),"=r"((r)[29]),"=r"((r)[30]),"=r"((r)[31])               \
        : "r"(ta))

static constexpr uint64_t DESC_BASE_SW128 =
    (uint64_t(2) << 61) | (uint64_t(1) << 46) | (uint64_t(64) << 32) | (uint64_t(1) << 16);
__device__ __forceinline__ uint64_t mk_desc(uint32_t a) {
    return DESC_BASE_SW128 | ((uint64_t)(a >> 4) & 0x3FFF);
}
__device__ __forceinline__ void mma_f16_ss(uint32_t d, uint64_t ad, uint64_t bd,
                                           uint32_t idesc, bool acc) {
    uint32_t en = acc ? 1u : 0u;
    asm volatile(
        "{ .reg .pred p; setp.ne.u32 p, %4, 0;\n\t"
        "tcgen05.mma.cta_group::1.kind::f16 [%0], %1, %2, %3, {%5,%5,%5,%5}, p; }"
        :: "r"(d), "l"(ad), "l"(bd), "r"(idesc), "r"(en), "r"(0u) : "memory");
}
__device__ __forceinline__ void cp16(uint32_t dst, const void* src) {
    asm volatile("cp.async.cg.shared.global [%0], [%1], 16;" :: "r"(dst), "l"(src));
}
#endif  // HAS_TC

// ---------------------------------------------------------------------------
// Kernel A1: W hi/lo reconstruction, coalesced + shfl reduce.
// Thread t loads float4 #t of P (fully coalesced); 16 consecutive lanes hold
// one row; butterfly-reduce within 16 lanes; lane (t%16==0) writes hi/lo.
// ---------------------------------------------------------------------------
__global__ void build_W_hilo(const float* __restrict__ P, const float* __restrict__ coef,
                             __nv_bfloat16* __restrict__ whi, __nv_bfloat16* __restrict__ wlo,
                             int nrows) {
    __shared__ float c[ID_DIM];
    if (threadIdx.x < ID_DIM) c[threadIdx.x] = coef[threadIdx.x];
    __syncthreads();
    const int total = nrows * 16;  // float4 count
    int t = blockIdx.x * blockDim.x + threadIdx.x;
    const int stride = gridDim.x * blockDim.x;
    for (; t < total; t += stride) {
        float4 v = reinterpret_cast<const float4*>(P)[t];
        const int q = (t & 15) * 4;
        float p = v.x * c[q] + v.y * c[q + 1] + v.z * c[q + 2] + v.w * c[q + 3];
        p += __shfl_xor_sync(0xffffffffu, p, 8);
        p += __shfl_xor_sync(0xffffffffu, p, 4);
        p += __shfl_xor_sync(0xffffffffu, p, 2);
        p += __shfl_xor_sync(0xffffffffu, p, 1);
        if ((threadIdx.x & 15) == 0) {
            const int row = t >> 4;
            __nv_bfloat16 h = __float2bfloat16_rn(p);
            whi[row] = h;
            wlo[row] = __float2bfloat16_rn(p - __bfloat162float(h));
        }
    }
}

// Kernel A2: bias (f32)
__global__ void build_bias(const float* __restrict__ P, const float* __restrict__ coef,
                           float* __restrict__ out, int n) {
    __shared__ float c[ID_DIM];
    if (threadIdx.x < ID_DIM) c[threadIdx.x] = coef[threadIdx.x];
    __syncthreads();
    int i = blockIdx.x * blockDim.x + threadIdx.x;
    if (i >= n) return;
    const float4* row = reinterpret_cast<const float4*>(P + (size_t)i * ID_DIM);
    float acc = 0.f;
#pragma unroll
    for (int j = 0; j < 16; ++j) {
        float4 v = row[j];
        acc += v.x * c[4 * j] + v.y * c[4 * j + 1] + v.z * c[4 * j + 2] + v.w * c[4 * j + 3];
    }
    out[i] = acc;
}

// ---------------------------------------------------------------------------
// Kernel B: split x into bf16 hi/lo (8 elems/thread)
// ---------------------------------------------------------------------------
__global__ void split_x(const float* __restrict__ x, __nv_bfloat16* __restrict__ hi,
                        __nv_bfloat16* __restrict__ lo, int n8) {
    int i = blockIdx.x * blockDim.x + threadIdx.x;
    if (i >= n8) return;
    const float4* xp = reinterpret_cast<const float4*>(x);
    float4 a = xp[2 * i], b = xp[2 * i + 1];
    float v[8] = {a.x, a.y, a.z, a.w, b.x, b.y, b.z, b.w};
    uint32_t uh[4], ul[4];
#pragma unroll
    for (int j = 0; j < 4; ++j) {
        __nv_bfloat16 h0 = __float2bfloat16_rn(v[2 * j]);
        __nv_bfloat16 h1 = __float2bfloat16_rn(v[2 * j + 1]);
        __nv_bfloat16 l0 = __float2bfloat16_rn(v[2 * j] - __bfloat162float(h0));
        __nv_bfloat16 l1 = __float2bfloat16_rn(v[2 * j + 1] - __bfloat162float(h1));
        uh[j] = ((uint32_t)__bfloat16_as_ushort(h1) << 16) | __bfloat16_as_ushort(h0);
        ul[j] = ((uint32_t)__bfloat16_as_ushort(l1) << 16) | __bfloat16_as_ushort(l0);
    }
    reinterpret_cast<uint4*>(hi)[i] = make_uint4(uh[0], uh[1], uh[2], uh[3]);
    reinterpret_cast<uint4*>(lo)[i] = make_uint4(ul[0], ul[1], ul[2], ul[3]);
}

// ---------------------------------------------------------------------------
// Kernel C: GEMM. tcgen05 path on 'a'-targets; SIMT hi/lo fallback otherwise.
// ---------------------------------------------------------------------------
#define BM 128
#define BN 128
#define KC 64
#define NCHUNK (DIM_K / KC)          // 32
#define STAGES 3
#define TILE_B (BM * 128)            // 16 KB per bf16 tile
#define STAGE_B (4 * TILE_B)         // 64 KB
#define SM_MBAR 16
#define SM_STAGE 1024
#define GEMM_SMEM (SM_STAGE + STAGES * STAGE_B)   // 197632 (fits either path)

__global__ __launch_bounds__(256, 1)
void gemm_tc(const __nv_bfloat16* __restrict__ Xhi, const __nv_bfloat16* __restrict__ Xlo,
             const __nv_bfloat16* __restrict__ Whi, const __nv_bfloat16* __restrict__ Wlo,
             const float* __restrict__ bias, float* __restrict__ C) {
    extern __shared__ char smem[];
    const int tid = threadIdx.x, wid = tid >> 5, lane = tid & 31;
    const int bn = blockIdx.x, bm = blockIdx.y;

#if HAS_TC
    const uint32_t sbase = smem_u32(smem);
    if (wid == 0) {
        TC_ALLOC(sbase, 128);
        TC_RELINQ();
    }
    if (tid == 0)
        for (int s = 0; s < STAGES; ++s) MBAR_INIT(sbase + SM_MBAR + 8 * s, 1);
    __syncthreads();
    uint32_t tmem;
    asm volatile("ld.shared.b32 %0, [%1];" : "=r"(tmem) : "r"(sbase));

    const __nv_bfloat16* bases[4] = {
        Xhi + (size_t)bm * BM * DIM_K, Xlo + (size_t)bm * BM * DIM_K,
        Whi + (size_t)bn * BN * DIM_K, Wlo + (size_t)bn * BN * DIM_K};

    auto load_chunk = [&](int chunk, int s) {
        const int k0 = chunk * KC;
        const uint32_t stg = sbase + SM_STAGE + s * STAGE_B;
#pragma unroll
        for (int t = 0; t < 16; ++t) {
            int idx = tid + t * 256;
            int tile = idx >> 10;
            int cid = idx & 1023;
            int r = cid >> 3, c = cid & 7;
            const void* src = bases[tile] + (size_t)r * DIM_K + k0 + c * 8;
            uint32_t off = (uint32_t)(r * 128 + c * 16);
            cp16(stg + tile * TILE_B + (off ^ ((off >> 3) & 0x70)), src);
        }
        asm volatile("cp.async.commit_group;" ::: "memory");
    };

    for (int i = 0; i < STAGES; ++i) load_chunk(i, i);

    int phase[STAGES] = {0, 0, 0};
    const uint32_t idesc = (1u << 4) | (1u << 7) | (1u << 10) | ((BN / 8) << 17) | ((BM / 16) << 24);
    bool first = true;

    for (int i = 0; i < NCHUNK; ++i) {
        const int s = i % STAGES;
        asm volatile("cp.async.wait_group %0;" :: "n"(STAGES - 1) : "memory");
        __syncthreads();
        asm volatile("fence.proxy.async.shared::cta;" ::: "memory");

        if (wid == 0 && elect_one()) {
            const uint32_t stg = sbase + SM_STAGE + s * STAGE_B;
            uint64_t dAh = mk_desc(stg), dAl = mk_desc(stg + TILE_B);
            uint64_t dBh = mk_desc(stg + 2 * TILE_B), dBl = mk_desc(stg + 3 * TILE_B);
            uint64_t ad[3] = {dAh, dAh, dAl};
            uint64_t bd[3] = {dBh, dBl, dBh};
#pragma unroll
            for (int m = 0; m < 3; ++m)
#pragma unroll
                for (int ks = 0; ks < 4; ++ks) {
                    mma_f16_ss(tmem, ad[m] + ks * 2, bd[m] + ks * 2, idesc, !first);
                    first = false;
                }
            TC_COMMIT(sbase + SM_MBAR + 8 * s);
        }

        if (i + STAGES < NCHUNK) {
            MBAR_WAIT(sbase + SM_MBAR + 8 * s, phase[s]);
            phase[s] ^= 1;
            load_chunk(i + STAGES, s);
        }
    }
    for (int i = NCHUNK - STAGES; i < NCHUNK; ++i) {
        const int s = i % STAGES;
        MBAR_WAIT(sbase + SM_MBAR + 8 * s, phase[s]);
        phase[s] ^= 1;
    }
    TC_FENCE_AFTER();
    __syncthreads();

    // Epilogue: TMEM -> regs -> smem transpose -> coalesced f32 stores + bias.
    if (wid < 4) {
        float* tbuf = reinterpret_cast<float*>(smem + SM_STAGE + wid * 32 * 33 * 4);
        float* Cb = C + ((size_t)bm * BM) * DIM_N + bn * BN;
        const int rsub = wid * 32;
#pragma unroll 1
        for (int sub = 0; sub < 4; ++sub) {
            const int cb = sub * 32;
            uint32_t regs[32];
            TC_LD_X32(regs, tmem + cb);
            TC_WAIT_LD();
#pragma unroll
            for (int j = 0; j < 32; ++j) tbuf[lane * 33 + j] = __uint_as_float(regs[j]);
            __syncwarp();
            const float bv = bias[bn * BN + cb + lane];
#pragma unroll
            for (int r = 0; r < 32; ++r)
                Cb[(size_t)(rsub + r) * DIM_N + cb + lane] = tbuf[r * 33 + lane] + bv;
            __syncwarp();
        }
    }
    __syncthreads();
    if (wid == 0) TC_DEALLOC(tmem, 128);

#else  // ------------------- SIMT hi/lo fallback (plain sm_103) -------------
    constexpr int K = DIM_K;
    float (*As)[132] = reinterpret_cast<float(*)[132]>(smem);
    float (*Bs)[132] = reinterpret_cast<float(*)[132]>(smem + 16 * 132 * sizeof(float));

    const int ty = tid >> 4, tx = tid & 15;
    const int lr = tid >> 1;              // 0..127 row
    const int kof = (tid & 1) * 8;        // 0 or 8 within BK=16

    const __nv_bfloat16* Ah = Xhi + (size_t)bm * BM * K;
    const __nv_bfloat16* Al = Xlo + (size_t)bm * BM * K;
    const __nv_bfloat16* Bh = Whi + (size_t)bn * BN * K;
    const __nv_bfloat16* Bl = Wlo + (size_t)bn * BN * K;

    float acc[8][8] = {};
    for (int k0 = 0; k0 < K; k0 += 16) {
        {
            uint4 vh = *reinterpret_cast<const uint4*>(Ah + (size_t)lr * K + k0 + kof);
            uint4 vl = *reinterpret_cast<const uint4*>(Al + (size_t)lr * K + k0 + kof);
            const __nv_bfloat162* ph = reinterpret_cast<const __nv_bfloat162*>(&vh);
            const __nv_bfloat162* pl = reinterpret_cast<const __nv_bfloat162*>(&vl);
#pragma unroll
            for (int w = 0; w < 4; ++w) {
                float2 h = __bfloat1622float2(ph[w]);
                float2 l = __bfloat1622float2(pl[w]);
                As[kof + 2 * w + 0][lr] = h.x + l.x;
                As[kof + 2 * w + 1][lr] = h.y + l.y;
            }
            vh = *reinterpret_cast<const uint4*>(Bh + (size_t)lr * K + k0 + kof);
            vl = *reinterpret_cast<const uint4*>(Bl + (size_t)lr * K + k0 + kof);
#pragma unroll
            for (int w = 0; w < 4; ++w) {
                float2 h = __bfloat1622float2(reinterpret_cast<const __nv_bfloat162*>(&vh)[w]);
                float2 l = __bfloat1622float2(reinterpret_cast<const __nv_bfloat162*>(&vl)[w]);
                Bs[kof + 2 * w + 0][lr] = h.x + l.x;
                Bs[kof + 2 * w + 1][lr] = h.y + l.y;
            }
        }
        __syncthreads();
#pragma unroll
        for (int kk = 0; kk < 16; ++kk) {
            float4 a0 = *reinterpret_cast<const float4*>(&As[kk][ty * 8 + 0]);
            float4 a1 = *reinterpret_cast<const float4*>(&As[kk][ty * 8 + 4]);
            float4 b0 = *reinterpret_cast<const float4*>(&Bs[kk][tx * 8 + 0]);
            float4 b1 = *reinterpret_cast<const float4*>(&Bs[kk][tx * 8 + 4]);
            float af[8] = {a0.x, a0.y, a0.z, a0.w, a1.x, a1.y, a1.z, a1.w};
            float bf[8] = {b0.x, b0.y, b0.z, b0.w, b1.x, b1.y, b1.z, b1.w};
#pragma unroll
            for (int i = 0; i < 8; ++i)
#pragma unroll
                for (int j = 0; j < 8; ++j)
                    acc[i][j] += af[i] * bf[j];
        }
        __syncthreads();
    }
#pragma unroll
    for (int i = 0; i < 8; ++i) {
        const int row = bm * BM + ty * 8 + i;
        float* Crow = C + (size_t)row * DIM_N + bn * BN + tx * 8;
        const float* brow = bias + bn * BN + tx * 8;
#pragma unroll
        for (int j4 = 0; j4 < 2; ++j4) {
            float4 v;
            v.x = acc[i][j4 * 4 + 0] + brow[j4 * 4 + 0];
            v.y = acc[i][j4 * 4 + 1] + brow[j4 * 4 + 1];
            v.z = acc[i][j4 * 4 + 2] + brow[j4 * 4 + 2];
            v.w = acc[i][j4 * 4 + 3] + brow[j4 * 4 + 3];
            *reinterpret_cast<float4*>(Crow + j4 * 4) = v;
        }
    }
#endif
}

// ---------------------------------------------------------------------------
extern "C" void kernel_launch(void* const* d_in, const int* in_sizes, int n_in,
                              void* d_out, int out_size) {
    const float* x     = (const float*)d_in[0];
    const float* P_w   = (const float*)d_in[1];
    const float* P_b   = (const float*)d_in[2];
    const float* wcoef = (const float*)d_in[3];
    const float* bcoef = (const float*)d_in[4];
    float* out = (float*)d_out;

    __nv_bfloat16 *Whi, *Wlo, *Xhi, *Xlo;
    float* bias;
    cudaGetSymbolAddress((void**)&Whi, g_Whi);
    cudaGetSymbolAddress((void**)&Wlo, g_Wlo);
    cudaGetSymbolAddress((void**)&Xhi, g_Xhi);
    cudaGetSymbolAddress((void**)&Xlo, g_Xlo);
    cudaGetSymbolAddress((void**)&bias, g_bias);

    cudaFuncSetAttribute(gemm_tc, cudaFuncAttributeMaxDynamicSharedMemorySize, GEMM_SMEM);

    build_W_hilo<<<8192, 256>>>(P_w, wcoef, Whi, Wlo, NW_ELEMS);
    build_bias<<<8, 256>>>(P_b, bcoef, bias, DIM_N);
    split_x<<<(BATCH_M * DIM_K / 8 + 255) / 256, 256>>>(x, Xhi, Xlo, BATCH_M * DIM_K / 8);

    dim3 grid(DIM_N / BN, BATCH_M / BM);
    gemm_tc<<<grid, 256, GEMM_SMEM>>>(Xhi, Xlo, Whi, Wlo, bias, out);

    (void)in_sizes; (void)n_in; (void)out_size;
}

// round 6
// speedup vs baseline: 4.7730x; 1.1959x over previous
#include <cuda_runtime.h>
#include <cuda_bf16.h>
#include <cstdint>

// Problem shapes (fixed)
#define BATCH_M   8192      // B*S
#define DIM_K     2048      // IN
#define DIM_N     2048      // OUT
#define ID_DIM    64
#define NW_ELEMS  (DIM_N * DIM_K)

#if defined(__CUDA_ARCH_FEAT_SM103_ALL) || defined(__CUDA_ARCH_FEAT_SM100_ALL) || \
    defined(__CUDA_ARCH_FEAT_SM101_ALL) || defined(__CUDA_ARCH_FEAT_SM110_ALL)
#define HAS_TC 1
#else
#define HAS_TC 0
#endif

// ---------------- scratch ----------------
__device__ __nv_bfloat16 g_Whi[NW_ELEMS];
__device__ __nv_bfloat16 g_Wlo[NW_ELEMS];
__device__ __nv_bfloat16 g_Xhi[BATCH_M * DIM_K];
__device__ __nv_bfloat16 g_Xlo[BATCH_M * DIM_K];
__device__ float         g_bias[DIM_N];

// ---------------- PTX helpers ----------------
__device__ __forceinline__ uint32_t smem_u32(const void* p) {
    uint32_t a;
    asm("{ .reg .u64 t; cvta.to.shared.u64 t, %1; cvt.u32.u64 %0, t; }" : "=r"(a) : "l"(p));
    return a;
}
#if HAS_TC
__device__ __forceinline__ uint32_t elect_one() {
    uint32_t p;
    asm volatile("{ .reg .pred p; elect.sync _|p, 0xFFFFFFFF; selp.b32 %0,1,0,p; }" : "=r"(p));
    return p;
}
#define MBAR_INIT(addr, cnt) \
    asm volatile("mbarrier.init.shared.b64 [%0], %1;" :: "r"(addr), "r"(cnt) : "memory")
#define MBAR_WAIT(addr, par) do {                                              \
    uint32_t _m = (addr), _p = (par), _d;                                      \
    asm volatile("{ .reg .pred p; mbarrier.try_wait.parity.acquire.cta.shared::cta.b64 p, [%1], %2; selp.b32 %0,1,0,p; }" \
        : "=r"(_d) : "r"(_m), "r"(_p) : "memory");                             \
    if (!_d) {                                                                 \
        asm volatile("{ .reg .pred P1; WL%=: mbarrier.try_wait.parity.acquire.cta.shared::cta.b64 P1, [%0], %1, 0x989680; @P1 bra.uni WD%=; bra.uni WL%=; WD%=: }" \
            :: "r"(_m), "r"(_p) : "memory");                                   \
    } } while (0)
#define TC_COMMIT(addr) \
    asm volatile("tcgen05.commit.cta_group::1.mbarrier::arrive::one.shared::cluster.b64 [%0];" :: "r"(addr) : "memory")
#define TC_ALLOC(saddr, n) \
    asm volatile("tcgen05.alloc.cta_group::1.sync.aligned.shared::cta.b32 [%0], %1;" :: "r"(saddr), "r"(n) : "memory")
#define TC_DEALLOC(t, n) \
    asm volatile("tcgen05.dealloc.cta_group::1.sync.aligned.b32 %0, %1;" :: "r"(t), "r"(n))
#define TC_RELINQ() asm volatile("tcgen05.relinquish_alloc_permit.cta_group::1.sync.aligned;")
#define TC_WAIT_LD() asm volatile("tcgen05.wait::ld.sync.aligned;" ::: "memory")
#define TC_FENCE_AFTER() asm volatile("tcgen05.fence::after_thread_sync;" ::: "memory")

#define TC_LD_X32(r, ta)                                                        \
    asm volatile("tcgen05.ld.sync.aligned.32x32b.x32.b32 "                      \
        "{%0,%1,%2,%3,%4,%5,%6,%7,%8,%9,%10,%11,%12,%13,%14,%15,"               \
        "%16,%17,%18,%19,%20,%21,%22,%23,%24,%25,%26,%27,%28,%29,%30,%31}, [%32];" \
        : "=r"((r)[0]),"=r"((r)[1]),"=r"((r)[2]),"=r"((r)[3]),                  \
          "=r"((r)[4]),"=r"((r)[5]),"=r"((r)[6]),"=r"((r)[7]),                  \
          "=r"((r)[8]),"=r"((r)[9]),"=r"((r)[10]),"=r"((r)[11]),                \
          "=r"((r)[12]),"=r"((r)[13]),"=r"((r)[14]),"=r"((r)[15]),              \
          "=r"((r)[16]),"=r"((r)[17]),"=r"((r)[18]),"=r"((r)[19]),              \
          "=r"((r)[20]),"=r"((r)[21]),"=r"((r)[22]),"=r"((r)[23]),              \
          "=r"((r)[24]),"=r"((r)[25]),"=r"((r)[26]),"=r"((r)[27]),              \
          "=r"((r)[28]),"=r"((r)[29]),"=r"((r)[30]),"=r"((r)[31])               \
        : "r"(ta))

static constexpr uint64_t DESC_BASE_SW128 =
    (uint64_t(2) << 61) | (uint64_t(1) << 46) | (uint64_t(64) << 32) | (uint64_t(1) << 16);
__device__ __forceinline__ uint64_t mk_desc(uint32_t a) {
    return DESC_BASE_SW128 | ((uint64_t)(a >> 4) & 0x3FFF);
}
__device__ __forceinline__ void mma_f16_ss(uint32_t d, uint64_t ad, uint64_t bd,
                                           uint32_t idesc, bool acc) {
    uint32_t en = acc ? 1u : 0u;
    asm volatile(
        "{ .reg .pred p; setp.ne.u32 p, %4, 0;\n\t"
        "tcgen05.mma.cta_group::1.kind::f16 [%0], %1, %2, %3, {%5,%5,%5,%5}, p; }"
        :: "r"(d), "l"(ad), "l"(bd), "r"(idesc), "r"(en), "r"(0u) : "memory");
}
__device__ __forceinline__ void cp16(uint32_t dst, const void* src) {
    asm volatile("cp.async.cg.shared.global [%0], [%1], 16;" :: "r"(dst), "l"(src));
}
// FIXED (R5 deadlock): .noinc — the default form increments the expected-arrival
// count at issue, so a barrier pre-initialized with count=128 never completes.
#define CP_ARRIVE(addr) \
    asm volatile("cp.async.mbarrier.arrive.noinc.shared.b64 [%0];" :: "r"(addr) : "memory")
#endif  // HAS_TC

// ---------------------------------------------------------------------------
// Kernel A1: W hi/lo reconstruction, coalesced, MLP=4 via unroll.
// ---------------------------------------------------------------------------
__global__ __launch_bounds__(256)
void build_W_hilo(const float* __restrict__ P, const float* __restrict__ coef,
                  __nv_bfloat16* __restrict__ whi, __nv_bfloat16* __restrict__ wlo,
                  int nrows) {
    __shared__ float c[ID_DIM];
    if (threadIdx.x < ID_DIM) c[threadIdx.x] = coef[threadIdx.x];
    __syncthreads();
    const int total = nrows * 16;          // float4 count
    const int S = gridDim.x * blockDim.x;  // multiple of 16
    int t = blockIdx.x * blockDim.x + threadIdx.x;
    const int q = (t & 15) * 4;
    const float4* P4 = reinterpret_cast<const float4*>(P);
    for (; t < total; t += 4 * S) {
        float4 v0 = P4[t];
        float4 v1 = P4[t + S];
        float4 v2 = P4[t + 2 * S];
        float4 v3 = P4[t + 3 * S];
        float p0 = v0.x * c[q] + v0.y * c[q + 1] + v0.z * c[q + 2] + v0.w * c[q + 3];
        float p1 = v1.x * c[q] + v1.y * c[q + 1] + v1.z * c[q + 2] + v1.w * c[q + 3];
        float p2 = v2.x * c[q] + v2.y * c[q + 1] + v2.z * c[q + 2] + v2.w * c[q + 3];
        float p3 = v3.x * c[q] + v3.y * c[q + 1] + v3.z * c[q + 2] + v3.w * c[q + 3];
#pragma unroll
        for (int d = 8; d >= 1; d >>= 1) {
            p0 += __shfl_xor_sync(0xffffffffu, p0, d);
            p1 += __shfl_xor_sync(0xffffffffu, p1, d);
            p2 += __shfl_xor_sync(0xffffffffu, p2, d);
            p3 += __shfl_xor_sync(0xffffffffu, p3, d);
        }
        if ((threadIdx.x & 15) == 0) {
            float pv[4] = {p0, p1, p2, p3};
#pragma unroll
            for (int j = 0; j < 4; ++j) {
                int row = (t + j * S) >> 4;
                __nv_bfloat16 h = __float2bfloat16_rn(pv[j]);
                whi[row] = h;
                wlo[row] = __float2bfloat16_rn(pv[j] - __bfloat162float(h));
            }
        }
    }
}

// Kernel A2: bias (f32)
__global__ void build_bias(const float* __restrict__ P, const float* __restrict__ coef,
                           float* __restrict__ out, int n) {
    __shared__ float c[ID_DIM];
    if (threadIdx.x < ID_DIM) c[threadIdx.x] = coef[threadIdx.x];
    __syncthreads();
    int i = blockIdx.x * blockDim.x + threadIdx.x;
    if (i >= n) return;
    const float4* row = reinterpret_cast<const float4*>(P + (size_t)i * ID_DIM);
    float acc = 0.f;
#pragma unroll
    for (int j = 0; j < 16; ++j) {
        float4 v = row[j];
        acc += v.x * c[4 * j] + v.y * c[4 * j + 1] + v.z * c[4 * j + 2] + v.w * c[4 * j + 3];
    }
    out[i] = acc;
}

// ---------------------------------------------------------------------------
// Kernel B: split x into bf16 hi/lo
// ---------------------------------------------------------------------------
__global__ void split_x(const float* __restrict__ x, __nv_bfloat16* __restrict__ hi,
                        __nv_bfloat16* __restrict__ lo, int n8) {
    int i = blockIdx.x * blockDim.x + threadIdx.x;
    if (i >= n8) return;
    const float4* xp = reinterpret_cast<const float4*>(x);
    float4 a = xp[2 * i], b = xp[2 * i + 1];
    float v[8] = {a.x, a.y, a.z, a.w, b.x, b.y, b.z, b.w};
    uint32_t uh[4], ul[4];
#pragma unroll
    for (int j = 0; j < 4; ++j) {
        __nv_bfloat16 h0 = __float2bfloat16_rn(v[2 * j]);
        __nv_bfloat16 h1 = __float2bfloat16_rn(v[2 * j + 1]);
        __nv_bfloat16 l0 = __float2bfloat16_rn(v[2 * j] - __bfloat162float(h0));
        __nv_bfloat16 l1 = __float2bfloat16_rn(v[2 * j + 1] - __bfloat162float(h1));
        uh[j] = ((uint32_t)__bfloat16_as_ushort(h1) << 16) | __bfloat16_as_ushort(h0);
        ul[j] = ((uint32_t)__bfloat16_as_ushort(l1) << 16) | __bfloat16_as_ushort(l0);
    }
    reinterpret_cast<uint4*>(hi)[i] = make_uint4(uh[0], uh[1], uh[2], uh[3]);
    reinterpret_cast<uint4*>(lo)[i] = make_uint4(ul[0], ul[1], ul[2], ul[3]);
}

// ---------------------------------------------------------------------------
// Kernel C: GEMM 128x256 tiles, warp-specialized, 2-stage pipeline.
// ---------------------------------------------------------------------------
#define BM 128
#define BN 256
#define KC 64
#define NCHUNK (DIM_K / KC)          // 32
#define STAGES 2
#define A_TILE 16384                 // 128 x 128B
#define B_TILE 32768                 // 256 x 128B
#define STAGE_B (2 * A_TILE + 2 * B_TILE)   // 96 KB
#define SM_MBAR 16                   // full0, full1, mdone0, mdone1 (8B each)
#define SM_STAGE 1024
#define GEMM_SMEM (SM_STAGE + STAGES * STAGE_B)   // 197632

__global__ __launch_bounds__(256, 1)
void gemm_tc(const __nv_bfloat16* __restrict__ Xhi, const __nv_bfloat16* __restrict__ Xlo,
             const __nv_bfloat16* __restrict__ Whi, const __nv_bfloat16* __restrict__ Wlo,
             const float* __restrict__ bias, float* __restrict__ C) {
    extern __shared__ char smem[];
    const int tid = threadIdx.x, wid = tid >> 5, lane = tid & 31;
    const int bn = blockIdx.x, bm = blockIdx.y;

#if HAS_TC
    const uint32_t sbase = smem_u32(smem);
    if (wid == 0) {
        TC_ALLOC(sbase, 256);
        TC_RELINQ();
    }
    if (tid == 0) {
        MBAR_INIT(sbase + SM_MBAR + 0, 128);   // full[0]
        MBAR_INIT(sbase + SM_MBAR + 8, 128);   // full[1]
        MBAR_INIT(sbase + SM_MBAR + 16, 1);    // mdone[0]
        MBAR_INIT(sbase + SM_MBAR + 24, 1);    // mdone[1]
    }
    __syncthreads();
    uint32_t tmem;
    asm volatile("ld.shared.b32 %0, [%1];" : "=r"(tmem) : "r"(sbase));

    const __nv_bfloat16* Ah = Xhi + (size_t)bm * BM * DIM_K;
    const __nv_bfloat16* Al = Xlo + (size_t)bm * BM * DIM_K;
    const __nv_bfloat16* Bh = Whi + (size_t)bn * BN * DIM_K;
    const __nv_bfloat16* Bl = Wlo + (size_t)bn * BN * DIM_K;

    if (wid == 0) {
        // ---------------- consumer: MMA issue ----------------
        if (elect_one()) {
            const uint32_t idesc =
                (1u << 4) | (1u << 7) | (1u << 10) | ((BN / 8) << 17) | ((BM / 16) << 24);
            int fph[2] = {0, 0};
            bool first = true;
            for (int i = 0; i < NCHUNK; ++i) {
                const int s = i & 1;
                MBAR_WAIT(sbase + SM_MBAR + 8 * s, fph[s]);
                fph[s] ^= 1;
                asm volatile("fence.proxy.async.shared::cta;" ::: "memory");
                const uint32_t stg = sbase + SM_STAGE + s * STAGE_B;
                uint64_t dAh = mk_desc(stg);
                uint64_t dAl = mk_desc(stg + A_TILE);
                uint64_t dBh = mk_desc(stg + 2 * A_TILE);
                uint64_t dBl = mk_desc(stg + 2 * A_TILE + B_TILE);
                uint64_t ad[3] = {dAh, dAh, dAl};
                uint64_t bd[3] = {dBh, dBl, dBh};
#pragma unroll
                for (int m = 0; m < 3; ++m)
#pragma unroll
                    for (int ks = 0; ks < 4; ++ks) {
                        mma_f16_ss(tmem, ad[m] + ks * 2, bd[m] + ks * 2, idesc, !first);
                        first = false;
                    }
                TC_COMMIT(sbase + SM_MBAR + 16 + 8 * s);
            }
            // chunk 31 is the 16th commit to mdone[1] -> completed phase 15, parity 1
            MBAR_WAIT(sbase + SM_MBAR + 24, 1);
        }
    } else if (wid <= 4) {
        // ---------------- producers: 4 warps, 128 threads ----------------
        const int ptid = tid - 32;
        int dph[2] = {0, 0};
        for (int i = 0; i < NCHUNK; ++i) {
            const int s = i & 1;
            if (i >= STAGES) {
                MBAR_WAIT(sbase + SM_MBAR + 16 + 8 * s, dph[s]);
                dph[s] ^= 1;
            }
            const int k0 = i * KC;
            const uint32_t stg = sbase + SM_STAGE + s * STAGE_B;
#pragma unroll
            for (int t = 0; t < 8; ++t) {       // A_hi
                int cid = ptid + t * 128;       // 0..1023
                int r = cid >> 3, cc = cid & 7;
                uint32_t off = (uint32_t)(r * 128 + cc * 16);
                cp16(stg + (off ^ ((off >> 3) & 0x70)), Ah + (size_t)r * DIM_K + k0 + cc * 8);
            }
#pragma unroll
            for (int t = 0; t < 8; ++t) {       // A_lo
                int cid = ptid + t * 128;
                int r = cid >> 3, cc = cid & 7;
                uint32_t off = (uint32_t)(r * 128 + cc * 16);
                cp16(stg + A_TILE + (off ^ ((off >> 3) & 0x70)),
                     Al + (size_t)r * DIM_K + k0 + cc * 8);
            }
#pragma unroll
            for (int t = 0; t < 16; ++t) {      // B_hi
                int cid = ptid + t * 128;       // 0..2047
                int r = cid >> 3, cc = cid & 7;
                uint32_t off = (uint32_t)(r * 128 + cc * 16);
                cp16(stg + 2 * A_TILE + (off ^ ((off >> 3) & 0x70)),
                     Bh + (size_t)r * DIM_K + k0 + cc * 8);
            }
#pragma unroll
            for (int t = 0; t < 16; ++t) {      // B_lo
                int cid = ptid + t * 128;
                int r = cid >> 3, cc = cid & 7;
                uint32_t off = (uint32_t)(r * 128 + cc * 16);
                cp16(stg + 2 * A_TILE + B_TILE + (off ^ ((off >> 3) & 0x70)),
                     Bl + (size_t)r * DIM_K + k0 + cc * 8);
            }
            CP_ARRIVE(sbase + SM_MBAR + 8 * s);
        }
    }
    __syncthreads();
    TC_FENCE_AFTER();

    // Epilogue: warps 0-3; 8 col-blocks of 32.
    if (wid < 4) {
        float* tbuf = reinterpret_cast<float*>(smem + SM_STAGE + wid * 32 * 33 * 4);
        float* Cb = C + ((size_t)bm * BM) * DIM_N + bn * BN;
        const int rsub = wid * 32;
#pragma unroll 1
        for (int sub = 0; sub < 8; ++sub) {
            const int cb = sub * 32;
            uint32_t regs[32];
            TC_LD_X32(regs, tmem + cb);
            TC_WAIT_LD();
#pragma unroll
            for (int j = 0; j < 32; ++j) tbuf[lane * 33 + j] = __uint_as_float(regs[j]);
            __syncwarp();
            const float bv = bias[bn * BN + cb + lane];
#pragma unroll
            for (int r = 0; r < 32; ++r)
                Cb[(size_t)(rsub + r) * DIM_N + cb + lane] = tbuf[r * 33 + lane] + bv;
            __syncwarp();
        }
    }
    __syncthreads();
    if (wid == 0) TC_DEALLOC(tmem, 256);

#else  // ------------------- SIMT fallback (never runs on GB300) ------------
    constexpr int K = DIM_K;
    float (*As)[132] = reinterpret_cast<float(*)[132]>(smem);
    float (*Bs)[132] = reinterpret_cast<float(*)[132]>(smem + 16 * 132 * sizeof(float));
    const int ty = tid >> 4, tx = tid & 15;
    const int lr = tid >> 1;
    const int kof = (tid & 1) * 8;

    for (int half = 0; half < 2; ++half) {
        const __nv_bfloat16* Ah = Xhi + (size_t)bm * BM * K;
        const __nv_bfloat16* Al = Xlo + (size_t)bm * BM * K;
        const __nv_bfloat16* Bh = Whi + ((size_t)bn * BN + half * 128) * K;
        const __nv_bfloat16* Bl = Wlo + ((size_t)bn * BN + half * 128) * K;
        float acc[8][8] = {};
        for (int k0 = 0; k0 < K; k0 += 16) {
            uint4 vh = *reinterpret_cast<const uint4*>(Ah + (size_t)lr * K + k0 + kof);
            uint4 vl = *reinterpret_cast<const uint4*>(Al + (size_t)lr * K + k0 + kof);
#pragma unroll
            for (int w = 0; w < 4; ++w) {
                float2 h = __bfloat1622float2(reinterpret_cast<const __nv_bfloat162*>(&vh)[w]);
                float2 l = __bfloat1622float2(reinterpret_cast<const __nv_bfloat162*>(&vl)[w]);
                As[kof + 2 * w + 0][lr] = h.x + l.x;
                As[kof + 2 * w + 1][lr] = h.y + l.y;
            }
            vh = *reinterpret_cast<const uint4*>(Bh + (size_t)lr * K + k0 + kof);
            vl = *reinterpret_cast<const uint4*>(Bl + (size_t)lr * K + k0 + kof);
#pragma unroll
            for (int w = 0; w < 4; ++w) {
                float2 h = __bfloat1622float2(reinterpret_cast<const __nv_bfloat162*>(&vh)[w]);
                float2 l = __bfloat1622float2(reinterpret_cast<const __nv_bfloat162*>(&vl)[w]);
                Bs[kof + 2 * w + 0][lr] = h.x + l.x;
                Bs[kof + 2 * w + 1][lr] = h.y + l.y;
            }
            __syncthreads();
#pragma unroll
            for (int kk = 0; kk < 16; ++kk) {
                float4 a0 = *reinterpret_cast<const float4*>(&As[kk][ty * 8 + 0]);
                float4 a1 = *reinterpret_cast<const float4*>(&As[kk][ty * 8 + 4]);
                float4 b0 = *reinterpret_cast<const float4*>(&Bs[kk][tx * 8 + 0]);
                float4 b1 = *reinterpret_cast<const float4*>(&Bs[kk][tx * 8 + 4]);
                float af[8] = {a0.x, a0.y, a0.z, a0.w, a1.x, a1.y, a1.z, a1.w};
                float bf[8] = {b0.x, b0.y, b0.z, b0.w, b1.x, b1.y, b1.z, b1.w};
#pragma unroll
                for (int i = 0; i < 8; ++i)
#pragma unroll
                    for (int j = 0; j < 8; ++j)
                        acc[i][j] += af[i] * bf[j];
            }
            __syncthreads();
        }
#pragma unroll
        for (int i = 0; i < 8; ++i) {
            const int row = bm * BM + ty * 8 + i;
            float* Crow = C + (size_t)row * DIM_N + bn * BN + half * 128 + tx * 8;
            const float* brow = bias + bn * BN + half * 128 + tx * 8;
#pragma unroll
            for (int j4 = 0; j4 < 2; ++j4) {
                float4 v;
                v.x = acc[i][j4 * 4 + 0] + brow[j4 * 4 + 0];
                v.y = acc[i][j4 * 4 + 1] + brow[j4 * 4 + 1];
                v.z = acc[i][j4 * 4 + 2] + brow[j4 * 4 + 2];
                v.w = acc[i][j4 * 4 + 3] + brow[j4 * 4 + 3];
                *reinterpret_cast<float4*>(Crow + j4 * 4) = v;
            }
        }
        __syncthreads();
    }
#endif
}

// ---------------------------------------------------------------------------
extern "C" void kernel_launch(void* const* d_in, const int* in_sizes, int n_in,
                              void* d_out, int out_size) {
    const float* x     = (const float*)d_in[0];
    const float* P_w   = (const float*)d_in[1];
    const float* P_b   = (const float*)d_in[2];
    const float* wcoef = (const float*)d_in[3];
    const float* bcoef = (const float*)d_in[4];
    float* out = (float*)d_out;

    __nv_bfloat16 *Whi, *Wlo, *Xhi, *Xlo;
    float* bias;
    cudaGetSymbolAddress((void**)&Whi, g_Whi);
    cudaGetSymbolAddress((void**)&Wlo, g_Wlo);
    cudaGetSymbolAddress((void**)&Xhi, g_Xhi);
    cudaGetSymbolAddress((void**)&Xlo, g_Xlo);
    cudaGetSymbolAddress((void**)&bias, g_bias);

    cudaFuncSetAttribute(gemm_tc, cudaFuncAttributeMaxDynamicSharedMemorySize, GEMM_SMEM);

    build_W_hilo<<<4096, 256>>>(P_w, wcoef, Whi, Wlo, NW_ELEMS);
    build_bias<<<8, 256>>>(P_b, bcoef, bias, DIM_N);
    split_x<<<(BATCH_M * DIM_K / 8 + 255) / 256, 256>>>(x, Xhi, Xlo, BATCH_M * DIM_K / 8);

    dim3 grid(DIM_N / BN, BATCH_M / BM);   // (8, 64)
    gemm_tc<<<grid, 256, GEMM_SMEM>>>(Xhi, Xlo, Whi, Wlo, bias, out);

    (void)in_sizes; (void)n_in; (void)out_size;
}